// round 16
// baseline (speedup 1.0000x reference)
#include <cuda_runtime.h>
#include <math.h>
#include <stdint.h>

// ---------------------------------------------------------------------------
// Problem constants
// ---------------------------------------------------------------------------
#define N_NODES 50000
#define IN_CH   128
#define OUT_CH  64
#define HEADS   4
#define C1      64
#define C2      32
#define HC1     (HEADS*C1)   // 256
#define HC2     (HEADS*C2)   // 128
#define E_EXT   800000
#define NEG_SLOPE 0.2f

#define NWARPS  4            // warps per block in the node kernel
#define SLOTW   64           // slots per node; P(deg>=64) ~ 1e-19 per node

// ---------------------------------------------------------------------------
// Scratch (device globals; no allocations allowed)
// ---------------------------------------------------------------------------
__device__ float g_xl1[(size_t)N_NODES * HC1];
__device__ float g_xr1[(size_t)N_NODES * HC1];
__device__ float g_h1 [(size_t)N_NODES * HC1];
__device__ float g_xl2[(size_t)N_NODES * HC2];
__device__ float g_xr2[(size_t)N_NODES * HC2];
__device__ float g_h2 [(size_t)N_NODES * HC2];

__device__ int g_cnt[N_NODES];
__device__ int g_colsrc[(size_t)N_NODES * SLOTW];

// ---------------------------------------------------------------------------
// tf32 / cp.async helpers
// ---------------------------------------------------------------------------
__device__ __forceinline__ uint32_t tf32r(float x) {
    uint32_t y;
    asm("cvt.rna.tf32.f32 %0, %1;" : "=r"(y) : "f"(x));
    return y;
}

__device__ __forceinline__ void mma_tf32(float c[4], const uint32_t a[4], const uint32_t b[2]) {
    asm volatile(
        "mma.sync.aligned.m16n8k8.row.col.f32.tf32.tf32.f32 "
        "{%0,%1,%2,%3}, {%4,%5,%6,%7}, {%8,%9}, {%0,%1,%2,%3};"
        : "+f"(c[0]), "+f"(c[1]), "+f"(c[2]), "+f"(c[3])
        : "r"(a[0]), "r"(a[1]), "r"(a[2]), "r"(a[3]), "r"(b[0]), "r"(b[1]));
}

__device__ __forceinline__ void cp16(void* smem, const void* g, bool pred) {
    uint32_t sa = (uint32_t)__cvta_generic_to_shared(smem);
    int sz = pred ? 16 : 0;
    asm volatile("cp.async.cg.shared.global [%0], [%1], 16, %2;"
                 :: "r"(sa), "l"(g), "r"(sz));
}
__device__ __forceinline__ void cp_commit() {
    asm volatile("cp.async.commit_group;");
}
template <int NPend>
__device__ __forceinline__ void cp_wait() {
    asm volatile("cp.async.wait_group %0;" :: "n"(NPend));
}

// ---------------------------------------------------------------------------
// cp.async-pipelined tf32 GEMM, DYNAMIC smem (allows NST=4, 59.4KB > 48KB
// static limit). Same indexing/accumulation order as the R8/R14 kernel.
// dual-B (fused Wl|Wr): blockIdx.x < nbx : Cl = A @ Bl, else Cr = A @ Br.
// BM=128, BK=16, 256 threads = 8 warps 4(M) x 2(N); warp tile 32 x (BN/2).
// ---------------------------------------------------------------------------
template <int BN, int NST>
__global__ void gemm_tf32_kernel(const float* __restrict__ A,
                                 const float* __restrict__ Bl,
                                 const float* __restrict__ Br,
                                 float* __restrict__ Cl,
                                 float* __restrict__ Cr,
                                 const float* __restrict__ bias,
                                 int M, int N, int K, int nbx)
{
    constexpr int NI   = BN / 16;
    constexpr int BPAD = BN + 8;
    constexpr int BJ   = BN / 64;

    extern __shared__ float dynsmem[];
    float (*As)[128][20]  = reinterpret_cast<float (*)[128][20]>(dynsmem);
    float (*Bs)[16][BPAD] = reinterpret_cast<float (*)[16][BPAD]>(dynsmem + NST * 128 * 20);

    int bx = blockIdx.x;
    const float* B = Bl;
    float* Co = Cl;
    if (bx >= nbx) { B = Br; Co = Cr; bx -= nbx; }

    const int tid  = threadIdx.x;
    const int wid  = tid >> 5;
    const int lane = tid & 31;
    const int wm   = wid & 3;
    const int wn   = wid >> 2;
    const int tq   = lane >> 2;
    const int tc   = lane & 3;

    const int m0 = blockIdx.y * 128;
    const int n0 = bx * BN;

    const int ar = tid >> 2;
    const int ac = (tid & 3) * 4;
    const int bk = tid >> 4;
    const int bn = (tid & 15) * 4 * BJ;

    const int T = K >> 4;

    float acc[2][NI][4];
    #pragma unroll
    for (int mi = 0; mi < 2; mi++)
        #pragma unroll
        for (int ni = 0; ni < NI; ni++)
            #pragma unroll
            for (int r = 0; r < 4; r++)
                acc[mi][ni][r] = 0.f;

    #pragma unroll
    for (int s = 0; s < NST - 1; s++) {
        if (s < T) {
            int k0 = s * 16;
            cp16(&As[s][ar][ac],      &A[(size_t)(m0 + ar) * K + k0 + ac],      m0 + ar < M);
            cp16(&As[s][ar + 64][ac], &A[(size_t)(m0 + ar + 64) * K + k0 + ac], m0 + ar + 64 < M);
            #pragma unroll
            for (int j = 0; j < BJ; j++)
                cp16(&Bs[s][bk][bn + 4 * j], &B[(size_t)(k0 + bk) * N + n0 + bn + 4 * j], true);
        }
        cp_commit();
    }

    for (int t = 0; t < T; t++) {
        cp_wait<NST - 2>();
        __syncthreads();

        {
            int f = t + NST - 1;
            if (f < T) {
                int st = f % NST;
                int k0 = f * 16;
                cp16(&As[st][ar][ac],      &A[(size_t)(m0 + ar) * K + k0 + ac],      m0 + ar < M);
                cp16(&As[st][ar + 64][ac], &A[(size_t)(m0 + ar + 64) * K + k0 + ac], m0 + ar + 64 < M);
                #pragma unroll
                for (int j = 0; j < BJ; j++)
                    cp16(&Bs[st][bk][bn + 4 * j], &B[(size_t)(k0 + bk) * N + n0 + bn + 4 * j], true);
            }
            cp_commit();
        }

        const int st = t % NST;
        #pragma unroll
        for (int ks = 0; ks < 2; ks++) {
            const int kc = ks * 8;
            uint32_t a[2][4], b[NI][2];
            #pragma unroll
            for (int mi = 0; mi < 2; mi++) {
                int rb = wm * 32 + mi * 16;
                a[mi][0] = tf32r(As[st][rb + tq    ][kc + tc    ]);
                a[mi][1] = tf32r(As[st][rb + tq + 8][kc + tc    ]);
                a[mi][2] = tf32r(As[st][rb + tq    ][kc + tc + 4]);
                a[mi][3] = tf32r(As[st][rb + tq + 8][kc + tc + 4]);
            }
            #pragma unroll
            for (int ni = 0; ni < NI; ni++) {
                int nb = wn * (BN / 2) + ni * 8;
                b[ni][0] = tf32r(Bs[st][kc + tc    ][nb + tq]);
                b[ni][1] = tf32r(Bs[st][kc + tc + 4][nb + tq]);
            }
            #pragma unroll
            for (int mi = 0; mi < 2; mi++)
                #pragma unroll
                for (int ni = 0; ni < NI; ni++)
                    mma_tf32(acc[mi][ni], a[mi], b[ni]);
        }
    }

    #pragma unroll
    for (int mi = 0; mi < 2; mi++) {
        #pragma unroll
        for (int ni = 0; ni < NI; ni++) {
            int gn = n0 + wn * (BN / 2) + ni * 8 + tc * 2;
            float b0 = 0.f, b1 = 0.f;
            if (bias) { b0 = bias[gn]; b1 = bias[gn + 1]; }
            int gm0 = m0 + wm * 32 + mi * 16 + tq;
            if (gm0 < M) {
                float2 v = make_float2(acc[mi][ni][0] + b0, acc[mi][ni][1] + b1);
                *(float2*)&Co[(size_t)gm0 * N + gn] = v;
            }
            int gm1 = gm0 + 8;
            if (gm1 < M) {
                float2 v = make_float2(acc[mi][ni][2] + b0, acc[mi][ni][3] + b1);
                *(float2*)&Co[(size_t)gm1 * N + gn] = v;
            }
        }
    }
}

// ---------------------------------------------------------------------------
// Slot-based adjacency build (no scans).
// ---------------------------------------------------------------------------
__global__ void zero_cnt_kernel(int* __restrict__ cnt)
{
    int i = blockIdx.x * blockDim.x + threadIdx.x;
    if (i < N_NODES) cnt[i] = 0;
}

__global__ void scatter_slots_kernel(const int* __restrict__ src,
                                     const int* __restrict__ dst,
                                     int* __restrict__ cnt,
                                     int* __restrict__ colsrc)
{
    int e = blockIdx.x * blockDim.x + threadIdx.x;
    if (e >= E_EXT) return;
    int d = dst[e];
    int pos = atomicAdd(&cnt[d], 1);
    colsrc[(size_t)d * SLOTW + pos] = src[e];
}

// ---------------------------------------------------------------------------
// SINGLE-PASS fused GATv2 edge phase — FROZEN R14 codegen (best measured).
// One warp per node, V float4s per lane, x2 edge unroll, self-loop hoisted.
// ---------------------------------------------------------------------------
template <int CH>
__global__ void gat_node_kernel(const int* __restrict__ cnt,
                                const int* __restrict__ colsrc,
                                const float* __restrict__ xl,
                                const float* __restrict__ xr,
                                const float* __restrict__ att,
                                const float* __restrict__ bias,
                                float* __restrict__ out)
{
    constexpr int HC  = 4 * CH;
    constexpr int PER = CH / 8;
    constexpr int V   = PER / 4;

    const int w    = threadIdx.x >> 5;
    const int lane = threadIdx.x & 31;
    const int node = blockIdx.x * NWARPS + w;
    if (node >= N_NODES) return;

    const int h    = lane >> 3;
    const int sub  = lane & 7;
    const int base = h * CH + sub * PER;

    float4 xr_v[V], att_v[V];
    #pragma unroll
    for (int q = 0; q < V; q++) {
        xr_v[q]  = *(const float4*)(xr  + (size_t)node * HC + base + 4 * q);
        att_v[q] = *(const float4*)(att + base + 4 * q);
    }

    const int deg = cnt[node];
    const int* slots = colsrc + (size_t)node * SLOTW;

    float4 acc[V];
    #pragma unroll
    for (int q = 0; q < V; q++) acc[q] = make_float4(0.f, 0.f, 0.f, 0.f);
    float s = 0.f;

    // ---- self loop first, hoisted ----
    {
        const float4* pl = (const float4*)(xl + (size_t)node * HC + base);
        float4 a[V];
        float sum = 0.f;
        #pragma unroll
        for (int q = 0; q < V; q++) {
            a[q] = pl[q];
            float e0 = a[q].x + xr_v[q].x;
            float e1 = a[q].y + xr_v[q].y;
            float e2 = a[q].z + xr_v[q].z;
            float e3 = a[q].w + xr_v[q].w;
            e0 = e0 > 0.f ? e0 : NEG_SLOPE * e0;
            e1 = e1 > 0.f ? e1 : NEG_SLOPE * e1;
            e2 = e2 > 0.f ? e2 : NEG_SLOPE * e2;
            e3 = e3 > 0.f ? e3 : NEG_SLOPE * e3;
            sum = fmaf(att_v[q].x, e0, sum);
            sum = fmaf(att_v[q].y, e1, sum);
            sum = fmaf(att_v[q].z, e2, sum);
            sum = fmaf(att_v[q].w, e3, sum);
        }
        sum += __shfl_xor_sync(0xffffffffu, sum, 1, 8);
        sum += __shfl_xor_sync(0xffffffffu, sum, 2, 8);
        sum += __shfl_xor_sync(0xffffffffu, sum, 4, 8);
        float p = __expf(sum);
        s += p;
        #pragma unroll
        for (int q = 0; q < V; q++) {
            acc[q].x = fmaf(p, a[q].x, acc[q].x);
            acc[q].y = fmaf(p, a[q].y, acc[q].y);
            acc[q].z = fmaf(p, a[q].z, acc[q].z);
            acc[q].w = fmaf(p, a[q].w, acc[q].w);
        }
    }

    // ---- edges: exactly deg iterations, x2 unroll ----
    int i = 0;
    for (; i + 2 <= deg; i += 2) {
        int s0 = slots[i];
        int s1 = slots[i + 1];
        const float4* p0 = (const float4*)(xl + (size_t)s0 * HC + base);
        const float4* p1 = (const float4*)(xl + (size_t)s1 * HC + base);

        float4 a0[V], a1[V];
        float sum0 = 0.f, sum1 = 0.f;
        #pragma unroll
        for (int q = 0; q < V; q++) { a0[q] = p0[q]; a1[q] = p1[q]; }
        #pragma unroll
        for (int q = 0; q < V; q++) {
            float e0, e1, e2, e3;
            e0 = a0[q].x + xr_v[q].x; e1 = a0[q].y + xr_v[q].y;
            e2 = a0[q].z + xr_v[q].z; e3 = a0[q].w + xr_v[q].w;
            e0 = e0 > 0.f ? e0 : NEG_SLOPE * e0;
            e1 = e1 > 0.f ? e1 : NEG_SLOPE * e1;
            e2 = e2 > 0.f ? e2 : NEG_SLOPE * e2;
            e3 = e3 > 0.f ? e3 : NEG_SLOPE * e3;
            sum0 = fmaf(att_v[q].x, e0, sum0); sum0 = fmaf(att_v[q].y, e1, sum0);
            sum0 = fmaf(att_v[q].z, e2, sum0); sum0 = fmaf(att_v[q].w, e3, sum0);

            e0 = a1[q].x + xr_v[q].x; e1 = a1[q].y + xr_v[q].y;
            e2 = a1[q].z + xr_v[q].z; e3 = a1[q].w + xr_v[q].w;
            e0 = e0 > 0.f ? e0 : NEG_SLOPE * e0;
            e1 = e1 > 0.f ? e1 : NEG_SLOPE * e1;
            e2 = e2 > 0.f ? e2 : NEG_SLOPE * e2;
            e3 = e3 > 0.f ? e3 : NEG_SLOPE * e3;
            sum1 = fmaf(att_v[q].x, e0, sum1); sum1 = fmaf(att_v[q].y, e1, sum1);
            sum1 = fmaf(att_v[q].z, e2, sum1); sum1 = fmaf(att_v[q].w, e3, sum1);
        }
        sum0 += __shfl_xor_sync(0xffffffffu, sum0, 1, 8);
        sum1 += __shfl_xor_sync(0xffffffffu, sum1, 1, 8);
        sum0 += __shfl_xor_sync(0xffffffffu, sum0, 2, 8);
        sum1 += __shfl_xor_sync(0xffffffffu, sum1, 2, 8);
        sum0 += __shfl_xor_sync(0xffffffffu, sum0, 4, 8);
        sum1 += __shfl_xor_sync(0xffffffffu, sum1, 4, 8);

        float pe0 = __expf(sum0);
        float pe1 = __expf(sum1);
        s += pe0 + pe1;
        #pragma unroll
        for (int q = 0; q < V; q++) {
            acc[q].x = fmaf(pe0, a0[q].x, acc[q].x);
            acc[q].y = fmaf(pe0, a0[q].y, acc[q].y);
            acc[q].z = fmaf(pe0, a0[q].z, acc[q].z);
            acc[q].w = fmaf(pe0, a0[q].w, acc[q].w);
            acc[q].x = fmaf(pe1, a1[q].x, acc[q].x);
            acc[q].y = fmaf(pe1, a1[q].y, acc[q].y);
            acc[q].z = fmaf(pe1, a1[q].z, acc[q].z);
            acc[q].w = fmaf(pe1, a1[q].w, acc[q].w);
        }
    }
    for (; i < deg; i++) {
        int sj = slots[i];
        const float4* pl = (const float4*)(xl + (size_t)sj * HC + base);
        float4 a[V];
        float sum = 0.f;
        #pragma unroll
        for (int q = 0; q < V; q++) {
            a[q] = pl[q];
            float e0 = a[q].x + xr_v[q].x;
            float e1 = a[q].y + xr_v[q].y;
            float e2 = a[q].z + xr_v[q].z;
            float e3 = a[q].w + xr_v[q].w;
            e0 = e0 > 0.f ? e0 : NEG_SLOPE * e0;
            e1 = e1 > 0.f ? e1 : NEG_SLOPE * e1;
            e2 = e2 > 0.f ? e2 : NEG_SLOPE * e2;
            e3 = e3 > 0.f ? e3 : NEG_SLOPE * e3;
            sum = fmaf(att_v[q].x, e0, sum);
            sum = fmaf(att_v[q].y, e1, sum);
            sum = fmaf(att_v[q].z, e2, sum);
            sum = fmaf(att_v[q].w, e3, sum);
        }
        sum += __shfl_xor_sync(0xffffffffu, sum, 1, 8);
        sum += __shfl_xor_sync(0xffffffffu, sum, 2, 8);
        sum += __shfl_xor_sync(0xffffffffu, sum, 4, 8);
        float p = __expf(sum);
        s += p;
        #pragma unroll
        for (int q = 0; q < V; q++) {
            acc[q].x = fmaf(p, a[q].x, acc[q].x);
            acc[q].y = fmaf(p, a[q].y, acc[q].y);
            acc[q].z = fmaf(p, a[q].z, acc[q].z);
            acc[q].w = fmaf(p, a[q].w, acc[q].w);
        }
    }

    const float inv = 1.f / (s + 1e-16f);

    float4* po = (float4*)(out + (size_t)node * HC + base);
    #pragma unroll
    for (int q = 0; q < V; q++) {
        float4 b = *(const float4*)(bias + base + 4 * q);
        float4 r;
        r.x = fmaf(acc[q].x, inv, b.x);
        r.y = fmaf(acc[q].y, inv, b.y);
        r.z = fmaf(acc[q].z, inv, b.z);
        r.w = fmaf(acc[q].w, inv, b.w);
        r.x = r.x > 0.f ? r.x : (__expf(r.x) - 1.f);
        r.y = r.y > 0.f ? r.y : (__expf(r.y) - 1.f);
        r.z = r.z > 0.f ? r.z : (__expf(r.z) - 1.f);
        r.w = r.w > 0.f ? r.w : (__expf(r.w) - 1.f);
        po[q] = r;
    }
}

// ---------------------------------------------------------------------------
// Launcher
// ---------------------------------------------------------------------------
static inline void* sym(const void* s) {
    void* p = nullptr;
    cudaGetSymbolAddress(&p, s);
    return p;
}

extern "C" void kernel_launch(void* const* d_in, const int* in_sizes, int n_in,
                              void* d_out, int out_size)
{
    const float* x    = (const float*)d_in[0];
    const int*   ei   = (const int*)d_in[1];
    const float* Wl1  = (const float*)d_in[2];
    const float* Wr1  = (const float*)d_in[3];
    const float* att1 = (const float*)d_in[4];
    const float* b1   = (const float*)d_in[5];
    const float* Wl2  = (const float*)d_in[6];
    const float* Wr2  = (const float*)d_in[7];
    const float* att2 = (const float*)d_in[8];
    const float* b2   = (const float*)d_in[9];
    const float* Wfc  = (const float*)d_in[10];
    const float* bfc  = (const float*)d_in[11];
    float* out = (float*)d_out;

    const int* src_arr = ei;
    const int* dst_arr = ei + E_EXT;

    float* xl1 = (float*)sym(g_xl1);
    float* xr1 = (float*)sym(g_xr1);
    float* h1  = (float*)sym(g_h1);
    float* xl2 = (float*)sym(g_xl2);
    float* xr2 = (float*)sym(g_xr2);
    float* h2  = (float*)sym(g_h2);
    int* cnt    = (int*)sym(g_cnt);
    int* colsrc = (int*)sym(g_colsrc);

    const int TB = 256;
    const int NB_NODES = (N_NODES + TB - 1) / TB;
    const int NB_EDGES = (E_EXT + TB - 1) / TB;
    const int NODE_BLOCKS = (N_NODES + NWARPS - 1) / NWARPS;
    const int MB = (N_NODES + 127) / 128;

    // GEMM dynamic smem: NST=4 stages (59392 B > 48KB static limit)
    constexpr int GEMM_NST  = 4;
    constexpr int GEMM_SMEM = (GEMM_NST * 128 * 20 + GEMM_NST * 16 * (64 + 8)) * 4;
    cudaFuncSetAttribute(gemm_tf32_kernel<64, GEMM_NST>,
                         cudaFuncAttributeMaxDynamicSharedMemorySize, GEMM_SMEM);

    // ---------- adjacency build ----------
    zero_cnt_kernel<<<NB_NODES, TB>>>(cnt);
    scatter_slots_kernel<<<NB_EDGES, TB>>>(src_arr, dst_arr, cnt, colsrc);

    // ---------- Layer 1 ----------
    gemm_tf32_kernel<64, GEMM_NST><<<dim3(2 * (HC1 / 64), MB), 256, GEMM_SMEM>>>(
        x, Wl1, Wr1, xl1, xr1, nullptr, N_NODES, HC1, IN_CH, HC1 / 64);
    gat_node_kernel<C1><<<NODE_BLOCKS, NWARPS * 32>>>(cnt, colsrc, xl1, xr1, att1, b1, h1);

    // ---------- Layer 2 ----------
    gemm_tf32_kernel<64, GEMM_NST><<<dim3(2 * (HC2 / 64), MB), 256, GEMM_SMEM>>>(
        h1, Wl2, Wr2, xl2, xr2, nullptr, N_NODES, HC2, HC1, HC2 / 64);
    gat_node_kernel<C2><<<NODE_BLOCKS, NWARPS * 32>>>(cnt, colsrc, xl2, xr2, att2, b2, h2);

    // ---------- Final linear ----------
    gemm_tf32_kernel<64, GEMM_NST><<<dim3(OUT_CH / 64, MB), 256, GEMM_SMEM>>>(
        h2, Wfc, nullptr, out, nullptr, bfc, N_NODES, OUT_CH, HC2, OUT_CH / 64);
}

// round 17
// speedup vs baseline: 1.0400x; 1.0400x over previous
#include <cuda_runtime.h>
#include <math.h>
#include <stdint.h>

// ---------------------------------------------------------------------------
// Problem constants
// ---------------------------------------------------------------------------
#define N_NODES 50000
#define IN_CH   128
#define OUT_CH  64
#define HEADS   4
#define C1      64
#define C2      32
#define HC1     (HEADS*C1)   // 256
#define HC2     (HEADS*C2)   // 128
#define E_EXT   800000
#define NEG_SLOPE 0.2f

#define NWARPS  2            // warps per block in the node kernel (finer blocks)
#define SLOTW   64           // slots per node; P(deg>=64) ~ 1e-19 per node

// ---------------------------------------------------------------------------
// Scratch (device globals; no allocations allowed)
// ---------------------------------------------------------------------------
__device__ float g_xl1[(size_t)N_NODES * HC1];
__device__ float g_xr1[(size_t)N_NODES * HC1];
__device__ float g_h1 [(size_t)N_NODES * HC1];
__device__ float g_xl2[(size_t)N_NODES * HC2];
__device__ float g_xr2[(size_t)N_NODES * HC2];
__device__ float g_h2 [(size_t)N_NODES * HC2];

__device__ int g_cnt[N_NODES];
__device__ int g_colsrc[(size_t)N_NODES * SLOTW];

// ---------------------------------------------------------------------------
// tf32 / cp.async helpers
// ---------------------------------------------------------------------------
__device__ __forceinline__ uint32_t tf32r(float x) {
    uint32_t y;
    asm("cvt.rna.tf32.f32 %0, %1;" : "=r"(y) : "f"(x));
    return y;
}

__device__ __forceinline__ void mma_tf32(float c[4], const uint32_t a[4], const uint32_t b[2]) {
    asm volatile(
        "mma.sync.aligned.m16n8k8.row.col.f32.tf32.tf32.f32 "
        "{%0,%1,%2,%3}, {%4,%5,%6,%7}, {%8,%9}, {%0,%1,%2,%3};"
        : "+f"(c[0]), "+f"(c[1]), "+f"(c[2]), "+f"(c[3])
        : "r"(a[0]), "r"(a[1]), "r"(a[2]), "r"(a[3]), "r"(b[0]), "r"(b[1]));
}

__device__ __forceinline__ void cp16(void* smem, const void* g, bool pred) {
    uint32_t sa = (uint32_t)__cvta_generic_to_shared(smem);
    int sz = pred ? 16 : 0;
    asm volatile("cp.async.cg.shared.global [%0], [%1], 16, %2;"
                 :: "r"(sa), "l"(g), "r"(sz));
}
__device__ __forceinline__ void cp_commit() {
    asm volatile("cp.async.commit_group;");
}
template <int NPend>
__device__ __forceinline__ void cp_wait() {
    asm volatile("cp.async.wait_group %0;" :: "n"(NPend));
}

// ---------------------------------------------------------------------------
// cp.async-pipelined tf32 GEMM — R14-proven config (static smem, NST=3).
// dual-B (fused Wl|Wr): blockIdx.x < nbx : Cl = A @ Bl, else Cr = A @ Br.
// BM=128, BK=16, 256 threads = 8 warps 4(M) x 2(N); warp tile 32 x (BN/2).
// ---------------------------------------------------------------------------
template <int BN, int NST>
__global__ void gemm_tf32_kernel(const float* __restrict__ A,
                                 const float* __restrict__ Bl,
                                 const float* __restrict__ Br,
                                 float* __restrict__ Cl,
                                 float* __restrict__ Cr,
                                 const float* __restrict__ bias,
                                 int M, int N, int K, int nbx)
{
    constexpr int NI   = BN / 16;
    constexpr int BPAD = BN + 8;
    constexpr int BJ   = BN / 64;

    __shared__ float As[NST][128][20];
    __shared__ float Bs[NST][16][BPAD];

    int bx = blockIdx.x;
    const float* B = Bl;
    float* Co = Cl;
    if (bx >= nbx) { B = Br; Co = Cr; bx -= nbx; }

    const int tid  = threadIdx.x;
    const int wid  = tid >> 5;
    const int lane = tid & 31;
    const int wm   = wid & 3;
    const int wn   = wid >> 2;
    const int tq   = lane >> 2;
    const int tc   = lane & 3;

    const int m0 = blockIdx.y * 128;
    const int n0 = bx * BN;

    const int ar = tid >> 2;
    const int ac = (tid & 3) * 4;
    const int bk = tid >> 4;
    const int bn = (tid & 15) * 4 * BJ;

    const int T = K >> 4;

    float acc[2][NI][4];
    #pragma unroll
    for (int mi = 0; mi < 2; mi++)
        #pragma unroll
        for (int ni = 0; ni < NI; ni++)
            #pragma unroll
            for (int r = 0; r < 4; r++)
                acc[mi][ni][r] = 0.f;

    #pragma unroll
    for (int s = 0; s < NST - 1; s++) {
        if (s < T) {
            int k0 = s * 16;
            cp16(&As[s][ar][ac],      &A[(size_t)(m0 + ar) * K + k0 + ac],      m0 + ar < M);
            cp16(&As[s][ar + 64][ac], &A[(size_t)(m0 + ar + 64) * K + k0 + ac], m0 + ar + 64 < M);
            #pragma unroll
            for (int j = 0; j < BJ; j++)
                cp16(&Bs[s][bk][bn + 4 * j], &B[(size_t)(k0 + bk) * N + n0 + bn + 4 * j], true);
        }
        cp_commit();
    }

    for (int t = 0; t < T; t++) {
        cp_wait<NST - 2>();
        __syncthreads();

        {
            int f = t + NST - 1;
            if (f < T) {
                int st = f % NST;
                int k0 = f * 16;
                cp16(&As[st][ar][ac],      &A[(size_t)(m0 + ar) * K + k0 + ac],      m0 + ar < M);
                cp16(&As[st][ar + 64][ac], &A[(size_t)(m0 + ar + 64) * K + k0 + ac], m0 + ar + 64 < M);
                #pragma unroll
                for (int j = 0; j < BJ; j++)
                    cp16(&Bs[st][bk][bn + 4 * j], &B[(size_t)(k0 + bk) * N + n0 + bn + 4 * j], true);
            }
            cp_commit();
        }

        const int st = t % NST;
        #pragma unroll
        for (int ks = 0; ks < 2; ks++) {
            const int kc = ks * 8;
            uint32_t a[2][4], b[NI][2];
            #pragma unroll
            for (int mi = 0; mi < 2; mi++) {
                int rb = wm * 32 + mi * 16;
                a[mi][0] = tf32r(As[st][rb + tq    ][kc + tc    ]);
                a[mi][1] = tf32r(As[st][rb + tq + 8][kc + tc    ]);
                a[mi][2] = tf32r(As[st][rb + tq    ][kc + tc + 4]);
                a[mi][3] = tf32r(As[st][rb + tq + 8][kc + tc + 4]);
            }
            #pragma unroll
            for (int ni = 0; ni < NI; ni++) {
                int nb = wn * (BN / 2) + ni * 8;
                b[ni][0] = tf32r(Bs[st][kc + tc    ][nb + tq]);
                b[ni][1] = tf32r(Bs[st][kc + tc + 4][nb + tq]);
            }
            #pragma unroll
            for (int mi = 0; mi < 2; mi++)
                #pragma unroll
                for (int ni = 0; ni < NI; ni++)
                    mma_tf32(acc[mi][ni], a[mi], b[ni]);
        }
    }

    #pragma unroll
    for (int mi = 0; mi < 2; mi++) {
        #pragma unroll
        for (int ni = 0; ni < NI; ni++) {
            int gn = n0 + wn * (BN / 2) + ni * 8 + tc * 2;
            float b0 = 0.f, b1 = 0.f;
            if (bias) { b0 = bias[gn]; b1 = bias[gn + 1]; }
            int gm0 = m0 + wm * 32 + mi * 16 + tq;
            if (gm0 < M) {
                float2 v = make_float2(acc[mi][ni][0] + b0, acc[mi][ni][1] + b1);
                *(float2*)&Co[(size_t)gm0 * N + gn] = v;
            }
            int gm1 = gm0 + 8;
            if (gm1 < M) {
                float2 v = make_float2(acc[mi][ni][2] + b0, acc[mi][ni][3] + b1);
                *(float2*)&Co[(size_t)gm1 * N + gn] = v;
            }
        }
    }
}

// ---------------------------------------------------------------------------
// Slot-based adjacency build (no scans).
// ---------------------------------------------------------------------------
__global__ void zero_cnt_kernel(int* __restrict__ cnt)
{
    int i = blockIdx.x * blockDim.x + threadIdx.x;
    if (i < N_NODES) cnt[i] = 0;
}

__global__ void scatter_slots_kernel(const int* __restrict__ src,
                                     const int* __restrict__ dst,
                                     int* __restrict__ cnt,
                                     int* __restrict__ colsrc)
{
    int e = blockIdx.x * blockDim.x + threadIdx.x;
    if (e >= E_EXT) return;
    int d = dst[e];
    int pos = atomicAdd(&cnt[d], 1);
    colsrc[(size_t)d * SLOTW + pos] = src[e];
}

// ---------------------------------------------------------------------------
// SINGLE-PASS fused GATv2 edge phase — FROZEN R14 codegen, NWARPS=2 blocks.
// One warp per node, V float4s per lane, x2 edge unroll, self-loop hoisted.
// ---------------------------------------------------------------------------
template <int CH>
__global__ void gat_node_kernel(const int* __restrict__ cnt,
                                const int* __restrict__ colsrc,
                                const float* __restrict__ xl,
                                const float* __restrict__ xr,
                                const float* __restrict__ att,
                                const float* __restrict__ bias,
                                float* __restrict__ out)
{
    constexpr int HC  = 4 * CH;
    constexpr int PER = CH / 8;
    constexpr int V   = PER / 4;

    const int w    = threadIdx.x >> 5;
    const int lane = threadIdx.x & 31;
    const int node = blockIdx.x * NWARPS + w;
    if (node >= N_NODES) return;

    const int h    = lane >> 3;
    const int sub  = lane & 7;
    const int base = h * CH + sub * PER;

    float4 xr_v[V], att_v[V];
    #pragma unroll
    for (int q = 0; q < V; q++) {
        xr_v[q]  = *(const float4*)(xr  + (size_t)node * HC + base + 4 * q);
        att_v[q] = *(const float4*)(att + base + 4 * q);
    }

    const int deg = cnt[node];
    const int* slots = colsrc + (size_t)node * SLOTW;

    float4 acc[V];
    #pragma unroll
    for (int q = 0; q < V; q++) acc[q] = make_float4(0.f, 0.f, 0.f, 0.f);
    float s = 0.f;

    // ---- self loop first, hoisted ----
    {
        const float4* pl = (const float4*)(xl + (size_t)node * HC + base);
        float4 a[V];
        float sum = 0.f;
        #pragma unroll
        for (int q = 0; q < V; q++) {
            a[q] = pl[q];
            float e0 = a[q].x + xr_v[q].x;
            float e1 = a[q].y + xr_v[q].y;
            float e2 = a[q].z + xr_v[q].z;
            float e3 = a[q].w + xr_v[q].w;
            e0 = e0 > 0.f ? e0 : NEG_SLOPE * e0;
            e1 = e1 > 0.f ? e1 : NEG_SLOPE * e1;
            e2 = e2 > 0.f ? e2 : NEG_SLOPE * e2;
            e3 = e3 > 0.f ? e3 : NEG_SLOPE * e3;
            sum = fmaf(att_v[q].x, e0, sum);
            sum = fmaf(att_v[q].y, e1, sum);
            sum = fmaf(att_v[q].z, e2, sum);
            sum = fmaf(att_v[q].w, e3, sum);
        }
        sum += __shfl_xor_sync(0xffffffffu, sum, 1, 8);
        sum += __shfl_xor_sync(0xffffffffu, sum, 2, 8);
        sum += __shfl_xor_sync(0xffffffffu, sum, 4, 8);
        float p = __expf(sum);
        s += p;
        #pragma unroll
        for (int q = 0; q < V; q++) {
            acc[q].x = fmaf(p, a[q].x, acc[q].x);
            acc[q].y = fmaf(p, a[q].y, acc[q].y);
            acc[q].z = fmaf(p, a[q].z, acc[q].z);
            acc[q].w = fmaf(p, a[q].w, acc[q].w);
        }
    }

    // ---- edges: exactly deg iterations, x2 unroll ----
    int i = 0;
    for (; i + 2 <= deg; i += 2) {
        int s0 = slots[i];
        int s1 = slots[i + 1];
        const float4* p0 = (const float4*)(xl + (size_t)s0 * HC + base);
        const float4* p1 = (const float4*)(xl + (size_t)s1 * HC + base);

        float4 a0[V], a1[V];
        float sum0 = 0.f, sum1 = 0.f;
        #pragma unroll
        for (int q = 0; q < V; q++) { a0[q] = p0[q]; a1[q] = p1[q]; }
        #pragma unroll
        for (int q = 0; q < V; q++) {
            float e0, e1, e2, e3;
            e0 = a0[q].x + xr_v[q].x; e1 = a0[q].y + xr_v[q].y;
            e2 = a0[q].z + xr_v[q].z; e3 = a0[q].w + xr_v[q].w;
            e0 = e0 > 0.f ? e0 : NEG_SLOPE * e0;
            e1 = e1 > 0.f ? e1 : NEG_SLOPE * e1;
            e2 = e2 > 0.f ? e2 : NEG_SLOPE * e2;
            e3 = e3 > 0.f ? e3 : NEG_SLOPE * e3;
            sum0 = fmaf(att_v[q].x, e0, sum0); sum0 = fmaf(att_v[q].y, e1, sum0);
            sum0 = fmaf(att_v[q].z, e2, sum0); sum0 = fmaf(att_v[q].w, e3, sum0);

            e0 = a1[q].x + xr_v[q].x; e1 = a1[q].y + xr_v[q].y;
            e2 = a1[q].z + xr_v[q].z; e3 = a1[q].w + xr_v[q].w;
            e0 = e0 > 0.f ? e0 : NEG_SLOPE * e0;
            e1 = e1 > 0.f ? e1 : NEG_SLOPE * e1;
            e2 = e2 > 0.f ? e2 : NEG_SLOPE * e2;
            e3 = e3 > 0.f ? e3 : NEG_SLOPE * e3;
            sum1 = fmaf(att_v[q].x, e0, sum1); sum1 = fmaf(att_v[q].y, e1, sum1);
            sum1 = fmaf(att_v[q].z, e2, sum1); sum1 = fmaf(att_v[q].w, e3, sum1);
        }
        sum0 += __shfl_xor_sync(0xffffffffu, sum0, 1, 8);
        sum1 += __shfl_xor_sync(0xffffffffu, sum1, 1, 8);
        sum0 += __shfl_xor_sync(0xffffffffu, sum0, 2, 8);
        sum1 += __shfl_xor_sync(0xffffffffu, sum1, 2, 8);
        sum0 += __shfl_xor_sync(0xffffffffu, sum0, 4, 8);
        sum1 += __shfl_xor_sync(0xffffffffu, sum1, 4, 8);

        float pe0 = __expf(sum0);
        float pe1 = __expf(sum1);
        s += pe0 + pe1;
        #pragma unroll
        for (int q = 0; q < V; q++) {
            acc[q].x = fmaf(pe0, a0[q].x, acc[q].x);
            acc[q].y = fmaf(pe0, a0[q].y, acc[q].y);
            acc[q].z = fmaf(pe0, a0[q].z, acc[q].z);
            acc[q].w = fmaf(pe0, a0[q].w, acc[q].w);
            acc[q].x = fmaf(pe1, a1[q].x, acc[q].x);
            acc[q].y = fmaf(pe1, a1[q].y, acc[q].y);
            acc[q].z = fmaf(pe1, a1[q].z, acc[q].z);
            acc[q].w = fmaf(pe1, a1[q].w, acc[q].w);
        }
    }
    for (; i < deg; i++) {
        int sj = slots[i];
        const float4* pl = (const float4*)(xl + (size_t)sj * HC + base);
        float4 a[V];
        float sum = 0.f;
        #pragma unroll
        for (int q = 0; q < V; q++) {
            a[q] = pl[q];
            float e0 = a[q].x + xr_v[q].x;
            float e1 = a[q].y + xr_v[q].y;
            float e2 = a[q].z + xr_v[q].z;
            float e3 = a[q].w + xr_v[q].w;
            e0 = e0 > 0.f ? e0 : NEG_SLOPE * e0;
            e1 = e1 > 0.f ? e1 : NEG_SLOPE * e1;
            e2 = e2 > 0.f ? e2 : NEG_SLOPE * e2;
            e3 = e3 > 0.f ? e3 : NEG_SLOPE * e3;
            sum = fmaf(att_v[q].x, e0, sum);
            sum = fmaf(att_v[q].y, e1, sum);
            sum = fmaf(att_v[q].z, e2, sum);
            sum = fmaf(att_v[q].w, e3, sum);
        }
        sum += __shfl_xor_sync(0xffffffffu, sum, 1, 8);
        sum += __shfl_xor_sync(0xffffffffu, sum, 2, 8);
        sum += __shfl_xor_sync(0xffffffffu, sum, 4, 8);
        float p = __expf(sum);
        s += p;
        #pragma unroll
        for (int q = 0; q < V; q++) {
            acc[q].x = fmaf(p, a[q].x, acc[q].x);
            acc[q].y = fmaf(p, a[q].y, acc[q].y);
            acc[q].z = fmaf(p, a[q].z, acc[q].z);
            acc[q].w = fmaf(p, a[q].w, acc[q].w);
        }
    }

    const float inv = 1.f / (s + 1e-16f);

    float4* po = (float4*)(out + (size_t)node * HC + base);
    #pragma unroll
    for (int q = 0; q < V; q++) {
        float4 b = *(const float4*)(bias + base + 4 * q);
        float4 r;
        r.x = fmaf(acc[q].x, inv, b.x);
        r.y = fmaf(acc[q].y, inv, b.y);
        r.z = fmaf(acc[q].z, inv, b.z);
        r.w = fmaf(acc[q].w, inv, b.w);
        r.x = r.x > 0.f ? r.x : (__expf(r.x) - 1.f);
        r.y = r.y > 0.f ? r.y : (__expf(r.y) - 1.f);
        r.z = r.z > 0.f ? r.z : (__expf(r.z) - 1.f);
        r.w = r.w > 0.f ? r.w : (__expf(r.w) - 1.f);
        po[q] = r;
    }
}

// ---------------------------------------------------------------------------
// Launcher
// ---------------------------------------------------------------------------
static inline void* sym(const void* s) {
    void* p = nullptr;
    cudaGetSymbolAddress(&p, s);
    return p;
}

extern "C" void kernel_launch(void* const* d_in, const int* in_sizes, int n_in,
                              void* d_out, int out_size)
{
    const float* x    = (const float*)d_in[0];
    const int*   ei   = (const int*)d_in[1];
    const float* Wl1  = (const float*)d_in[2];
    const float* Wr1  = (const float*)d_in[3];
    const float* att1 = (const float*)d_in[4];
    const float* b1   = (const float*)d_in[5];
    const float* Wl2  = (const float*)d_in[6];
    const float* Wr2  = (const float*)d_in[7];
    const float* att2 = (const float*)d_in[8];
    const float* b2   = (const float*)d_in[9];
    const float* Wfc  = (const float*)d_in[10];
    const float* bfc  = (const float*)d_in[11];
    float* out = (float*)d_out;

    const int* src_arr = ei;
    const int* dst_arr = ei + E_EXT;

    float* xl1 = (float*)sym(g_xl1);
    float* xr1 = (float*)sym(g_xr1);
    float* h1  = (float*)sym(g_h1);
    float* xl2 = (float*)sym(g_xl2);
    float* xr2 = (float*)sym(g_xr2);
    float* h2  = (float*)sym(g_h2);
    int* cnt    = (int*)sym(g_cnt);
    int* colsrc = (int*)sym(g_colsrc);

    const int TB = 256;
    const int NB_NODES = (N_NODES + TB - 1) / TB;
    const int NB_EDGES = (E_EXT + TB - 1) / TB;
    const int NODE_BLOCKS = (N_NODES + NWARPS - 1) / NWARPS;
    const int MB = (N_NODES + 127) / 128;

    // ---------- adjacency build ----------
    zero_cnt_kernel<<<NB_NODES, TB>>>(cnt);
    scatter_slots_kernel<<<NB_EDGES, TB>>>(src_arr, dst_arr, cnt, colsrc);

    // ---------- Layer 1 ----------
    gemm_tf32_kernel<64, 3><<<dim3(2 * (HC1 / 64), MB), 256>>>(
        x, Wl1, Wr1, xl1, xr1, nullptr, N_NODES, HC1, IN_CH, HC1 / 64);
    gat_node_kernel<C1><<<NODE_BLOCKS, NWARPS * 32>>>(cnt, colsrc, xl1, xr1, att1, b1, h1);

    // ---------- Layer 2 ----------
    gemm_tf32_kernel<64, 3><<<dim3(2 * (HC2 / 64), MB), 256>>>(
        h1, Wl2, Wr2, xl2, xr2, nullptr, N_NODES, HC2, HC1, HC2 / 64);
    gat_node_kernel<C2><<<NODE_BLOCKS, NWARPS * 32>>>(cnt, colsrc, xl2, xr2, att2, b2, h2);

    // ---------- Final linear ----------
    gemm_tf32_kernel<64, 3><<<dim3(OUT_CH / 64, MB), 256>>>(
        h2, Wfc, nullptr, out, nullptr, bfc, N_NODES, OUT_CH, HC2, OUT_CH / 64);
}